// round 3
// baseline (speedup 1.0000x reference)
#include <cuda_runtime.h>

// Inputs (metadata order): z [8192*128] f32 (UNUSED), risk [B] f32, time [B] f32, event [B] i32.
// Output: single f32 scalar = mean hinge over pairs (time[i] < time[j] && event[i]==1).

#define TPB    256
#define I_TILE 1024          // i rows per block (before event-compaction; ~512 survive)
#define JCH    128           // j rows per block (smem-resident)
#define NWARPS (TPB / 32)
#define IPT    4             // raw i rows per thread during compaction (I_TILE/TPB)

__device__ double       g_total;   // zeroed at module load; reset by last block each launch
__device__ double       g_count;
__device__ unsigned int g_done;

__global__ __launch_bounds__(TPB) void k_fused(const float* __restrict__ risk,
                                               const float* __restrict__ time_,
                                               const int*   __restrict__ event,
                                               float*       __restrict__ out,
                                               int n, unsigned int nblocks) {
    __shared__ float2 sj[JCH];        // (risk_j, time_j)
    __shared__ float2 sci[I_TILE];    // compacted (risk_i + 1, time_i) for event==1
    __shared__ int    sscan[TPB];
    __shared__ int    s_ne;
    __shared__ float  swsum[NWARPS];
    __shared__ int    swcnt[NWARPS];

    const int tid = threadIdx.x;
    const int i0  = blockIdx.x * I_TILE;
    const int j0  = blockIdx.y * JCH;

    // ---- load j-chunk into shared ----
    if (tid < JCH) {
        int j = j0 + tid;
        float rj = 0.0f, tj = -1.0f;      // tj=-1 < any real time -> never contributes
        if (j < n) { rj = risk[j]; tj = time_[j]; }
        sj[tid] = make_float2(rj, tj);
    }

    // ---- per-block event-compaction of this i-tile (deterministic order) ----
    float rr[IPT], tt[IPT];
    int   ev[IPT];
    int   cloc = 0;
    #pragma unroll
    for (int t = 0; t < IPT; t++) {
        int ii = i0 + IPT * tid + t;
        int e  = (ii < n) && (event[ii] == 1);
        ev[t] = e;
        rr[t] = 0.0f; tt[t] = 0.0f;
        if (e) { rr[t] = risk[ii] + 1.0f; tt[t] = time_[ii]; }
        cloc += e;
    }
    sscan[tid] = cloc;
    __syncthreads();
    #pragma unroll
    for (int off = 1; off < TPB; off <<= 1) {
        int v   = sscan[tid];
        int add = (tid >= off) ? sscan[tid - off] : 0;
        __syncthreads();
        sscan[tid] = v + add;
        __syncthreads();
    }
    {
        int pos = sscan[tid] - cloc;
        #pragma unroll
        for (int t = 0; t < IPT; t++) {
            if (ev[t]) { sci[pos] = make_float2(rr[t], tt[t]); pos++; }
        }
        if (tid == TPB - 1) s_ne = sscan[TPB - 1];
    }
    __syncthreads();
    const int ne = s_ne;

    // ---- pair loop: 2 register-resident i's per thread per pass ----
    float s0 = 0.f, s1 = 0.f;
    int   c0 = 0,   c1 = 0;

    for (int base = 0; base < ne; base += 2 * TPB) {
        int ia = base + tid;
        int ib = base + TPB + tid;
        float r0 = 0.0f, t0 = 3.0f;   // inert: time in [0,1) so tj > 3 never true
        float r1 = 0.0f, t1 = 3.0f;
        if (ia < ne) { float2 u = sci[ia]; r0 = u.x; t0 = u.y; }
        if (ib < ne) { float2 u = sci[ib]; r1 = u.x; t1 = u.y; }

        #pragma unroll 8
        for (int k = 0; k < JCH; k++) {
            float2 v = sj[k];
            if (v.y > t0) { s0 += fmaxf(r0 - v.x, 0.0f); c0++; }
            if (v.y > t1) { s1 += fmaxf(r1 - v.x, 0.0f); c1++; }
        }
    }

    // ---- reduction: warp shfl -> smem -> warp0 -> device-global RED ----
    float s = s0 + s1;
    int   c = c0 + c1;
    #pragma unroll
    for (int off = 16; off >= 1; off >>= 1) {
        s += __shfl_down_sync(0xffffffffu, s, off);
        c += __shfl_down_sync(0xffffffffu, c, off);
    }
    if ((tid & 31) == 0) { swsum[tid >> 5] = s; swcnt[tid >> 5] = c; }
    __syncthreads();
    if (tid == 0) {
        #pragma unroll
        for (int w = 1; w < NWARPS; w++) { s += swsum[w]; c += swcnt[w]; }
        atomicAdd(&g_total, (double)s);   // no-return use -> RED.F64
        atomicAdd(&g_count, (double)c);
        __threadfence();
        unsigned int prev = atomicAdd(&g_done, 1u);
        if (prev == nblocks - 1) {
            __threadfence();
            double tt_ = *(volatile double*)&g_total;
            double cc_ = *(volatile double*)&g_count;
            out[0] = (cc_ == 0.0) ? 0.0f : (float)(tt_ / cc_);
            g_total = 0.0;                 // reset: replay-idempotent
            g_count = 0.0;
            g_done  = 0u;
        }
    }
}

extern "C" void kernel_launch(void* const* d_in, const int* in_sizes, int n_in,
                              void* d_out, int out_size) {
    const float* risk  = (const float*)d_in[1];
    const float* time_ = (const float*)d_in[2];
    const int*   event = (const int*)d_in[3];
    const int n = in_sizes[1];

    dim3 grid((n + I_TILE - 1) / I_TILE, (n + JCH - 1) / JCH);
    unsigned int nblocks = grid.x * grid.y;

    k_fused<<<grid, TPB>>>(risk, time_, event, (float*)d_out, n, nblocks);
}

// round 4
// speedup vs baseline: 1.0155x; 1.0155x over previous
#include <cuda_runtime.h>

// Inputs (metadata order): z [8192*128] f32 (UNUSED), risk [B] f32, time [B] f32, event [B] i32.
// Output: single f32 scalar = mean hinge over pairs (time[i] < time[j] && event[i]==1).
//
// Key facts exploited:
//  - time >= 0, so (t_j > t_i) == (bits(t_j) > bits(t_i)) as signed ints (alu pipe).
//  - branch-free inner loop (ternaries only) -> no BSSY/BSYNC divergence.
//  - grid 8 x 74 = 592 blocks = exactly 4 per SM: one perfectly balanced wave.

#define TPB    256
#define I_TILE 1024          // raw i rows per block (pre-compaction; ~512 survive)
#define IPT    4             // I_TILE / TPB
#define JCH    112           // j rows per block (74 * 112 = 8288 >= 8192)
#define NWARPS (TPB / 32)

__device__ double       g_total;   // zeroed at module load; reset by last block each launch
__device__ double       g_count;
__device__ unsigned int g_done;

__global__ __launch_bounds__(TPB) void k_fused(const float* __restrict__ risk,
                                               const float* __restrict__ time_,
                                               const int*   __restrict__ event,
                                               float*       __restrict__ out,
                                               int n) {
    __shared__ float2 sj[JCH];         // (risk_j, time_j)
    __shared__ float2 sci[I_TILE];     // compacted (risk_i + 1, time_i), event==1 only
    __shared__ int    scnt[IPT * NWARPS];
    __shared__ float  swsum[NWARPS];
    __shared__ int    swcnt[NWARPS];

    const int tid  = threadIdx.x;
    const int lane = tid & 31;
    const int w    = tid >> 5;
    const int i0   = blockIdx.x * I_TILE;
    const int j0   = blockIdx.y * JCH;

    // ---- load j-slice into shared ----
    if (tid < JCH) {
        int j = j0 + tid;
        float rj = 0.0f, tj = -1.0f;   // bits(-1.0f) < 0 -> never passes tjb > it
        if (j < n) { rj = risk[j]; tj = time_[j]; }
        sj[tid] = make_float2(rj, tj);
    }

    // ---- ballot-based event-compaction of this i-tile ----
    bool  ev[IPT];
    float rr[IPT], tt[IPT];
    unsigned bal[IPT];
    #pragma unroll
    for (int t = 0; t < IPT; t++) {
        int ii = i0 + t * TPB + tid;            // coalesced
        bool e = (ii < n) && (event[ii] == 1);
        ev[t] = e;
        rr[t] = 0.0f; tt[t] = 0.0f;
        if (e) { rr[t] = risk[ii] + 1.0f; tt[t] = time_[ii]; }
        bal[t] = __ballot_sync(0xffffffffu, e);
        if (lane == 0) scnt[t * NWARPS + w] = __popc(bal[t]);
    }
    __syncthreads();

    int ne = 0;
    int pre[IPT];
    {
        int run = 0;
        #pragma unroll
        for (int t = 0; t < IPT; t++) {
            pre[t] = -1;
            #pragma unroll
            for (int q = 0; q < NWARPS; q++) {
                if (t * NWARPS + q == t * NWARPS + w && pre[t] < 0) {}
                // prefix for (t, w): sum of all slots before it
            }
        }
        // simple linear walk over the 32 slots accumulating prefix + total
        #pragma unroll
        for (int t = 0; t < IPT; t++) {
            #pragma unroll
            for (int q = 0; q < NWARPS; q++) {
                int idx = t * NWARPS + q;
                if (idx == t * NWARPS + w) pre[t] = run;   // exclusive prefix for my warp, segment t
                run += scnt[idx];
            }
        }
        ne = run;
    }
    #pragma unroll
    for (int t = 0; t < IPT; t++) {
        if (ev[t]) {
            int pos = pre[t] + __popc(bal[t] & ((1u << lane) - 1u));
            sci[pos] = make_float2(rr[t], tt[t]);
        }
    }
    __syncthreads();

    // ---- branch-free pair loop: 2 register-resident i's per thread per pass ----
    float s0 = 0.f, s1 = 0.f;
    int   c0 = 0,   c1 = 0;

    for (int base = 0; base < ne; base += 2 * TPB) {
        float r0 = 0.0f; int it0 = 0x7FFFFFFF;   // inert lane: compare never true
        float r1 = 0.0f; int it1 = 0x7FFFFFFF;
        int ia = base + tid;
        int ib = base + TPB + tid;
        if (ia < ne) { float2 u = sci[ia]; r0 = u.x; it0 = __float_as_int(u.y); }
        if (ib < ne) { float2 u = sci[ib]; r1 = u.x; it1 = __float_as_int(u.y); }

        #pragma unroll 8
        for (int k = 0; k < JCH; k++) {
            float2 v  = sj[k];
            int   tjb = __float_as_int(v.y);
            float h0  = fmaxf(r0 - v.x, 0.0f);
            float h1  = fmaxf(r1 - v.x, 0.0f);
            bool  p0  = tjb > it0;
            bool  p1  = tjb > it1;
            s0 += p0 ? h0 : 0.0f;
            s1 += p1 ? h1 : 0.0f;
            c0 += (int)p0;
            c1 += (int)p1;
        }
    }

    // ---- reduction: warp shfl -> smem -> thread 0 -> device-global RED ----
    float s = s0 + s1;
    int   c = c0 + c1;
    #pragma unroll
    for (int off = 16; off >= 1; off >>= 1) {
        s += __shfl_down_sync(0xffffffffu, s, off);
        c += __shfl_down_sync(0xffffffffu, c, off);
    }
    if (lane == 0) { swsum[w] = s; swcnt[w] = c; }
    __syncthreads();
    if (tid == 0) {
        #pragma unroll
        for (int q = 1; q < NWARPS; q++) { s += swsum[q]; c += swcnt[q]; }
        atomicAdd(&g_total, (double)s);
        atomicAdd(&g_count, (double)c);
        __threadfence();
        unsigned int nblocks = gridDim.x * gridDim.y;
        unsigned int prev = atomicAdd(&g_done, 1u);
        if (prev == nblocks - 1) {
            __threadfence();
            double tt_ = *(volatile double*)&g_total;
            double cc_ = *(volatile double*)&g_count;
            out[0] = (cc_ == 0.0) ? 0.0f : (float)(tt_ / cc_);
            g_total = 0.0;                 // reset: replay-idempotent
            g_count = 0.0;
            g_done  = 0u;
        }
    }
}

extern "C" void kernel_launch(void* const* d_in, const int* in_sizes, int n_in,
                              void* d_out, int out_size) {
    const float* risk  = (const float*)d_in[1];
    const float* time_ = (const float*)d_in[2];
    const int*   event = (const int*)d_in[3];
    const int n = in_sizes[1];

    dim3 grid((n + I_TILE - 1) / I_TILE, (n + JCH - 1) / JCH);
    k_fused<<<grid, TPB>>>(risk, time_, event, (float*)d_out, n);
}